// round 6
// baseline (speedup 1.0000x reference)
#include <cuda_runtime.h>
#include <math.h>

#define B_SZ 64
#define S_SZ 1024
#define I_SZ 512
#define H_SZ 512

// ---------------- static device scratch (no allocations allowed) ----------------
__device__ float g_xg  [(size_t)S_SZ * 3 * B_SZ * H_SZ];  // [S][3][B][H]
__device__ float g_ys0 [(size_t)S_SZ * B_SZ * H_SZ];      // layer-0 fwd outputs [S][B][H]
__device__ float g_ys1 [(size_t)S_SZ * B_SZ * H_SZ];      // layer-1 fwd outputs
__device__ float g_hb0 [B_SZ * H_SZ];
__device__ float g_hb1 [B_SZ * H_SZ];
__device__ float g_wpk0[3 * 512 * 512];                   // packed Wh layer0: [g][k/4][col][4]
__device__ float g_wpk1[3 * 512 * 512];                   // packed Wh layer1

// ---------------- tf32 helpers ----------------
__device__ __forceinline__ unsigned f2tf(float x) {
    unsigned u;
    asm("cvt.rna.tf32.f32 %0, %1;" : "=r"(u) : "f"(x));
    return u;
}

__device__ __forceinline__ void mma8(float* c, const unsigned* a, unsigned b0, unsigned b1) {
    asm volatile(
        "mma.sync.aligned.m16n8k8.row.col.f32.tf32.tf32.f32 "
        "{%0,%1,%2,%3}, {%4,%5,%6,%7}, {%8,%9}, {%0,%1,%2,%3};"
        : "+f"(c[0]), "+f"(c[1]), "+f"(c[2]), "+f"(c[3])
        : "r"(a[0]), "r"(a[1]), "r"(a[2]), "r"(a[3]), "r"(b0), "r"(b1));
}

// ---------------- projection GEMM (verified working, unchanged) ----------------
// out[s][g][b][h] = sum_k X(b,s,k) * W[g][k][h] + bias[g][h]
__global__ void __launch_bounds__(256) proj_kernel(
    const float* __restrict__ X, long sb, long ss,
    const float* __restrict__ W, const float* __restrict__ bias,
    float* __restrict__ out, int Srows)
{
    __shared__ float As[128][36];
    __shared__ float Bs[32][136];

    const int M  = Srows * B_SZ;
    const int m0 = blockIdx.y * 128;
    const int n0 = blockIdx.x * 128;
    const int g  = n0 >> 9;
    const int h0 = n0 & 511;
    const float* Wg = W + (size_t)g * H_SZ * H_SZ;

    const int tid  = threadIdx.x;
    const int lane = tid & 31;
    const int warp = tid >> 5;
    const int wm   = warp & 3;
    const int wn   = warp >> 2;

    float acc[2][8][4];
#pragma unroll
    for (int i = 0; i < 2; i++)
#pragma unroll
        for (int jf = 0; jf < 8; jf++)
#pragma unroll
            for (int k = 0; k < 4; k++) acc[i][jf][k] = 0.f;

    for (int k0 = 0; k0 < H_SZ; k0 += 32) {
#pragma unroll
        for (int i = 0; i < 4; i++) {
            int idx = tid + i * 256;
            int row = idx >> 3;
            int kk  = (idx & 7) << 2;
            float4 v = make_float4(0.f, 0.f, 0.f, 0.f);
            int r = m0 + row;
            if (r < M) {
                int s = r >> 6, b = r & 63;
                v = *(const float4*)(X + (size_t)b * sb + (size_t)s * ss + k0 + kk);
            }
            As[row][kk + 0] = __uint_as_float(f2tf(v.x));
            As[row][kk + 1] = __uint_as_float(f2tf(v.y));
            As[row][kk + 2] = __uint_as_float(f2tf(v.z));
            As[row][kk + 3] = __uint_as_float(f2tf(v.w));
        }
#pragma unroll
        for (int i = 0; i < 4; i++) {
            int idx = tid + i * 256;
            int kk  = idx >> 5;
            int nn  = (idx & 31) << 2;
            float4 v = *(const float4*)(Wg + (size_t)(k0 + kk) * H_SZ + h0 + nn);
            Bs[kk][nn + 0] = __uint_as_float(f2tf(v.x));
            Bs[kk][nn + 1] = __uint_as_float(f2tf(v.y));
            Bs[kk][nn + 2] = __uint_as_float(f2tf(v.z));
            Bs[kk][nn + 3] = __uint_as_float(f2tf(v.w));
        }
        __syncthreads();

#pragma unroll
        for (int kq = 0; kq < 4; kq++) {
            const int kr = kq * 8;
            unsigned a[2][4];
#pragma unroll
            for (int mf = 0; mf < 2; mf++) {
                int rb = wm * 32 + mf * 16 + (lane >> 2);
                int c  = kr + (lane & 3);
                a[mf][0] = __float_as_uint(As[rb][c]);
                a[mf][1] = __float_as_uint(As[rb + 8][c]);
                a[mf][2] = __float_as_uint(As[rb][c + 4]);
                a[mf][3] = __float_as_uint(As[rb + 8][c + 4]);
            }
#pragma unroll
            for (int nf = 0; nf < 8; nf++) {
                int cb = wn * 64 + nf * 8 + (lane >> 2);
                unsigned b0 = __float_as_uint(Bs[kr + (lane & 3)][cb]);
                unsigned b1 = __float_as_uint(Bs[kr + (lane & 3) + 4][cb]);
                mma8(acc[0][nf], a[0], b0, b1);
                mma8(acc[1][nf], a[1], b0, b1);
            }
        }
        __syncthreads();
    }

#pragma unroll
    for (int mf = 0; mf < 2; mf++) {
#pragma unroll
        for (int nf = 0; nf < 8; nf++) {
            int col = wn * 64 + nf * 8 + ((lane & 3) << 1);
            int h   = h0 + col;
            float b0v = bias[g * H_SZ + h];
            float b1v = bias[g * H_SZ + h + 1];
            int r = m0 + wm * 32 + mf * 16 + (lane >> 2);
            if (r < M) {
                int s = r >> 6, b = r & 63;
                float* o = out + ((size_t)(s * 3 + g) * B_SZ + b) * H_SZ + h;
                o[0] = acc[mf][nf][0] + b0v;
                o[1] = acc[mf][nf][1] + b1v;
            }
            int r2 = r + 8;
            if (r2 < M) {
                int s = r2 >> 6, b = r2 & 63;
                float* o = out + ((size_t)(s * 3 + g) * B_SZ + b) * H_SZ + h;
                o[0] = acc[mf][nf][2] + b0v;
                o[1] = acc[mf][nf][3] + b1v;
            }
        }
    }
}

// ---------------- Wh pre-pack: [g][k][col] -> [g][k/4][col][k%4] ----------------
__global__ void __launch_bounds__(256) pack_wh(const float* __restrict__ Wh,
                                               float* __restrict__ wpk)
{
    int idx = blockIdx.x * 256 + threadIdx.x;   // over 3*512*512
    if (idx < 3 * 512 * 512) {
        int col = idx & 511;
        int k   = (idx >> 9) & 511;
        int g   = idx >> 18;
        wpk[((((size_t)g * 128 + (k >> 2)) * 512 + col) << 2) + (k & 3)] = Wh[idx];
    }
}

// ---------------- persistent-per-launch recurrent scan with HW clusters ----------------
// grid (8, 8): x = colgroup (64 cols), y = bgrp (8 batches). Cluster = 8 CTAs along x
// (one bgrp). HW cluster.sync per step — no software barriers anywhere.
#define SCAN_SMEM_BYTES ((4096 + 12288) * 4)   // hs [8][512] + red [8][3][8][64] = 64 KB

__global__ void __launch_bounds__(512, 1) __cluster_dims__(8, 1, 1)
scan_kernel(const float* __restrict__ xg,    // [S][3][B][H]
            const float4* __restrict__ wpk,  // [3][128][512] float4 (packed)
            float* __restrict__ ys,          // [S][B][H]
            int S)
{
    extern __shared__ float sm[];
    float*  hs  = sm;           // 4096 floats
    float*  red = sm + 4096;    // 12288 floats: [kc][g][b][jc]
    float4* hs4 = (float4*)hs;

    const int tid  = threadIdx.x;
    const int lane = tid & 31;
    const int w    = tid >> 5;
    const int kc   = w >> 1;              // 0..7 : 64 K-rows each
    const int jh   = w & 1;               // 0..1 : 32-col half
    const int cgrp = blockIdx.x;          // 0..7
    const int bgrp = blockIdx.y;          // 0..7
    const int j0   = cgrp << 6;
    const int b0   = bgrp << 3;
    const int col  = j0 + (jh << 5) + lane;
    const int k4b  = kc << 4;             // float4-granule k base
    const int jc   = (jh << 5) + lane;

    // gate-stage mapping: thread -> (batch gb, col gj)
    const int gb = tid >> 6;              // 0..7
    const int gj = tid & 63;              // 0..63

    const float4* w0p = wpk + ((size_t)(0 * 128 + k4b) << 9) + col;
    const float4* w1p = wpk + ((size_t)(1 * 128 + k4b) << 9) + col;
    const float4* w2p = wpk + ((size_t)(2 * 128 + k4b) << 9) + col;

    for (int s = 0; s < S; s++) {
        // stage h_prev [8][512]; bypass L1 (peer-CTA writes, cluster-scope visibility)
        if (s == 0) {
            for (int i = tid; i < 1024; i += 512) hs4[i] = make_float4(0.f, 0.f, 0.f, 0.f);
        } else {
            const float4* hp = (const float4*)(ys + ((size_t)(s - 1) * B_SZ + b0) * H_SZ);
            for (int i = tid; i < 1024; i += 512) hs4[i] = __ldcg(hp + i);
        }
        __syncthreads();

        float acc[3][8];
#pragma unroll
        for (int g = 0; g < 3; g++)
#pragma unroll
            for (int b = 0; b < 8; b++) acc[g][b] = 0.f;

#pragma unroll 4
        for (int t = 0; t < 16; t++) {
            float4 w0 = __ldg(w0p + ((size_t)t << 9));
            float4 w1 = __ldg(w1p + ((size_t)t << 9));
            float4 w2 = __ldg(w2p + ((size_t)t << 9));
            const int k4 = k4b + t;
#pragma unroll
            for (int b = 0; b < 8; b++) {
                float4 h4 = hs4[b * 128 + k4];
                acc[0][b] += h4.x * w0.x + h4.y * w0.y + h4.z * w0.z + h4.w * w0.w;
                acc[1][b] += h4.x * w1.x + h4.y * w1.y + h4.z * w1.z + h4.w * w1.w;
                acc[2][b] += h4.x * w2.x + h4.y * w2.y + h4.z * w2.z + h4.w * w2.w;
            }
        }

        // cross-kc partials
#pragma unroll
        for (int g = 0; g < 3; g++)
#pragma unroll
            for (int b = 0; b < 8; b++)
                red[((kc * 3 + g) * 8 + b) * 64 + jc] = acc[g][b];
        __syncthreads();

        float a0 = 0.f, a1 = 0.f, a2 = 0.f;
#pragma unroll
        for (int c = 0; c < 8; c++) {
            a0 += red[((c * 3 + 0) * 8 + gb) * 64 + gj];
            a1 += red[((c * 3 + 1) * 8 + gb) * 64 + gj];
            a2 += red[((c * 3 + 2) * 8 + gb) * 64 + gj];
        }

        float hprev = hs[gb * 512 + j0 + gj];

        const size_t xi = ((size_t)s * 3 * B_SZ + (b0 + gb)) * H_SZ + j0 + gj;
        float x0 = xg[xi];
        float x1 = xg[xi + (size_t)B_SZ * H_SZ];
        float x2 = xg[xi + (size_t)2 * B_SZ * H_SZ];

        float r  = 1.f / (1.f + expf(-(x0 + a0)));
        float z  = 1.f / (1.f + expf(-(x1 + a1)));
        float n  = tanhf(x2 + r * a2);
        float hn = (1.f - z) * n + z * hprev;

        ys[((size_t)s * B_SZ + b0 + gb) * H_SZ + j0 + gj] = hn;

        // HW cluster barrier: release/acquire at cluster scope + L1D flush.
        asm volatile("barrier.cluster.arrive.aligned;" ::: "memory");
        asm volatile("barrier.cluster.wait.aligned;"   ::: "memory");
    }
}

// ---------------- backward shortcut: one GRU step with h = 0 ----------------
__global__ void __launch_bounds__(128) bwd_step(
    const float* __restrict__ xin, long bstride, long off,
    const float* __restrict__ Wi, const float* __restrict__ bias,
    float* __restrict__ hout)
{
    int h = blockIdx.x * 128 + threadIdx.x;
    int b = blockIdx.y;
    const float* xr = xin + (size_t)b * bstride + off;
    const float* W1 = Wi + (size_t)1 * 512 * 512 + h;
    const float* W2 = Wi + (size_t)2 * 512 * 512 + h;
    float a1 = 0.f, a2 = 0.f;
    for (int k = 0; k < 512; k++) {
        float xv = __ldg(xr + k);
        a1 += xv * W1[(size_t)k * 512];
        a2 += xv * W2[(size_t)k * 512];
    }
    float z = 1.f / (1.f + expf(-(a1 + bias[512 + h])));
    float n = tanhf(a2 + bias[1024 + h]);
    hout[(size_t)b * 512 + h] = (1.f - z) * n;
}

// ---------------- final FC ----------------
__global__ void __launch_bounds__(128) fc_kernel(
    const float* __restrict__ ysl, const float* __restrict__ hb,
    const float* __restrict__ fw, const float* __restrict__ fb,
    float* __restrict__ out)
{
    int o = blockIdx.x * 128 + threadIdx.x;
    int b = blockIdx.y;
    float acc = fb[o];
    const float* f0 = ysl + (size_t)b * 512;
    const float* h0 = hb  + (size_t)b * 512;
    for (int jq = 0; jq < 512; jq++) acc += f0[jq] * fw[(size_t)jq * 512 + o];
    for (int jq = 0; jq < 512; jq++) acc += h0[jq] * fw[(size_t)(512 + jq) * 512 + o];
    out[(size_t)b * 512 + o] = acc;
}

// ---------------- launch ----------------
extern "C" void kernel_launch(void* const* d_in, const int* in_sizes, int n_in,
                              void* d_out, int out_size)
{
    (void)in_sizes; (void)n_in; (void)out_size;
    const float* x  = (const float*)d_in[0];   // [64][1024][512]
    const float* Wi = (const float*)d_in[1];   // [2][2][3][512][512]
    const float* Wh = (const float*)d_in[2];   // [2][2][3][512][512]
    const float* bb = (const float*)d_in[3];   // [2][2][3][512]
    const float* fw = (const float*)d_in[4];   // [1024][512]
    const float* fb = (const float*)d_in[5];   // [512]
    float* out = (float*)d_out;

    float *xg, *ys0, *ys1, *hb0, *hb1, *wpk0, *wpk1;
    cudaGetSymbolAddress((void**)&xg,   g_xg);
    cudaGetSymbolAddress((void**)&ys0,  g_ys0);
    cudaGetSymbolAddress((void**)&ys1,  g_ys1);
    cudaGetSymbolAddress((void**)&hb0,  g_hb0);
    cudaGetSymbolAddress((void**)&hb1,  g_hb1);
    cudaGetSymbolAddress((void**)&wpk0, g_wpk0);
    cudaGetSymbolAddress((void**)&wpk1, g_wpk1);

    cudaFuncSetAttribute(scan_kernel, cudaFuncAttributeMaxDynamicSharedMemorySize,
                         SCAN_SMEM_BYTES);

    const size_t WSLAB = (size_t)3 * 512 * 512;
    const size_t BSLAB = (size_t)3 * 512;
    const size_t YSSTEP = (size_t)B_SZ * H_SZ;

    dim3 pgrid(12, 512);
    dim3 sgrid(8, 8);
    int  pkblocks = (3 * 512 * 512 + 255) / 256;

    // pre-pack recurrent weights for both forward layers
    pack_wh<<<pkblocks, 256>>>(Wh + 0 * WSLAB, wpk0);
    pack_wh<<<pkblocks, 256>>>(Wh + 2 * WSLAB, wpk1);

    // ---- forward layer 0 ----
    proj_kernel<<<pgrid, 256>>>(x, (long)S_SZ * I_SZ, (long)I_SZ,
                                Wi + 0 * WSLAB, bb + 0 * BSLAB, xg, S_SZ);
    scan_kernel<<<sgrid, 512, SCAN_SMEM_BYTES>>>(xg, (const float4*)wpk0, ys0, S_SZ);

    // ---- forward layer 1 ----
    proj_kernel<<<pgrid, 256>>>(ys0, (long)H_SZ, (long)B_SZ * H_SZ,
                                Wi + 2 * WSLAB, bb + 2 * BSLAB, xg, S_SZ);
    scan_kernel<<<sgrid, 512, SCAN_SMEM_BYTES>>>(xg, (const float4*)wpk1, ys1, S_SZ);

    // ---- backward direction collapses to two single GRU steps (h0 = 0) ----
    dim3 bgrid(4, 64);
    bwd_step<<<bgrid, 128>>>(x, (long)S_SZ * I_SZ, (long)(S_SZ - 1) * I_SZ,
                             Wi + 1 * WSLAB, bb + 1 * BSLAB, hb0);
    bwd_step<<<bgrid, 128>>>(hb0, (long)H_SZ, 0L,
                             Wi + 3 * WSLAB, bb + 3 * BSLAB, hb1);

    // ---- final FC on [out_f[:, -1], out_b[:, -1]] ----
    fc_kernel<<<bgrid, 128>>>(ys1 + (size_t)(S_SZ - 1) * YSSTEP, hb1, fw, fb, out);
}